// round 5
// baseline (speedup 1.0000x reference)
#include <cuda_runtime.h>

#define N_NODES_MAX 100000
#define N_EDGES_MAX 1300000
#define F 64
#define N_GRAPHS 64
#define SCAN_BS 512

// ---------------- scratch (static device globals; no allocs allowed) -------
__device__ float g_h[(size_t)N_NODES_MAX * F];     // 25.6 MB (layer-1 output)
__device__ int   g_deg[N_NODES_MAX];
__device__ int   g_rowptr[N_NODES_MAX + 1];
__device__ int   g_cursor[N_NODES_MAX];
__device__ int   g_csr[N_EDGES_MAX];               // src ids grouped by dst
__device__ unsigned long long g_state[512];        // lookback scan states
__device__ float g_sum[N_GRAPHS];
__device__ float g_cnt[N_GRAPHS];
__device__ int   g_e64;   // 1 if edge_index is int64, else int32
__device__ int   g_b64;   // 1 if batch is int64, else int32

// ---------------- packed f32x2 helpers (FFMA2 path, sm_103a) ---------------
__device__ __forceinline__ unsigned long long pack2(float a, float b) {
    unsigned long long r;
    asm("mov.b64 %0, {%1, %2};" : "=l"(r) : "f"(a), "f"(b));
    return r;
}
__device__ __forceinline__ unsigned long long splat2(float a) {
    unsigned long long r;
    asm("mov.b64 %0, {%1, %1};" : "=l"(r) : "f"(a));
    return r;
}
__device__ __forceinline__ void unpack2(unsigned long long v, float& a, float& b) {
    asm("mov.b64 {%0, %1}, %2;" : "=f"(a), "=f"(b) : "l"(v));
}
__device__ __forceinline__ unsigned long long ffma2(unsigned long long a,
                                                    unsigned long long b,
                                                    unsigned long long c) {
    unsigned long long r;
    asm("fma.rn.f32x2 %0, %1, %2, %3;" : "=l"(r) : "l"(a), "l"(b), "l"(c));
    return r;
}

// ---------------- init: zero deg/state/pool + dtype detection --------------
__global__ void init_kernel(const void* __restrict__ ei,
                            const void* __restrict__ batch, int nNodes) {
    int i = blockIdx.x * blockDim.x + threadIdx.x;
    if (i < nNodes) g_deg[i] = 0;
    if (i < N_GRAPHS) {
        g_sum[i] = 0.f;
        g_cnt[i] = 0.f;
    }
    if (i < 512) g_state[i] = 0ULL;
    if (i == 0) {
        const long long* p = (const long long*)ei;
        bool ok = true;
        for (int k = 0; k < 4; k++) {
            long long v = p[k];
            if (v < 0 || v >= N_NODES_MAX) ok = false;
        }
        g_e64 = ok ? 1 : 0;
        const long long* q = (const long long*)batch;
        int M = nNodes / 2;
        bool okb = true;
        for (int k = M - 4; k < M; k++) {
            long long v = q[k];
            if (v < 0 || v >= N_GRAPHS) okb = false;
        }
        g_b64 = okb ? 1 : 0;
    }
}

// ---------------- histogram of dst (4 edges per thread) --------------------
__global__ void __launch_bounds__(256) hist_kernel(const void* __restrict__ ei,
                                                   int nE) {
    int t = blockIdx.x * 256 + threadIdx.x;
    int e = t * 4;
    if (e >= nE) return;
    if (g_e64) {
        const long long* d = (const long long*)ei + nE;
        if (e + 3 < nE) {
            longlong2 a = *(const longlong2*)(d + e);
            longlong2 b = *(const longlong2*)(d + e + 2);
            atomicAdd(&g_deg[(int)a.x], 1);
            atomicAdd(&g_deg[(int)a.y], 1);
            atomicAdd(&g_deg[(int)b.x], 1);
            atomicAdd(&g_deg[(int)b.y], 1);
        } else {
            for (int k = e; k < nE; k++) atomicAdd(&g_deg[(int)d[k]], 1);
        }
    } else {
        const int* d = (const int*)ei + nE;
        if (e + 3 < nE) {
            int4 a = *(const int4*)(d + e);
            atomicAdd(&g_deg[a.x], 1);
            atomicAdd(&g_deg[a.y], 1);
            atomicAdd(&g_deg[a.z], 1);
            atomicAdd(&g_deg[a.w], 1);
        } else {
            for (int k = e; k < nE; k++) atomicAdd(&g_deg[d[k]], 1);
        }
    }
}

// ---------------- single-pass scan (decoupled lookback) --------------------
__global__ void __launch_bounds__(SCAN_BS) scan_kernel(int nNodes) {
    int tid = threadIdx.x, bid = blockIdx.x;
    int lane = tid & 31, w = tid >> 5;
    int i = bid * SCAN_BS + tid;
    int v = (i < nNodes) ? g_deg[i] : 0;

    int x = v;
#pragma unroll
    for (int o = 1; o < 32; o <<= 1) {
        int y = __shfl_up_sync(0xffffffffu, x, o);
        if (lane >= o) x += y;
    }
    __shared__ int wsum[SCAN_BS / 32];
    __shared__ int sprefix;
    if (lane == 31) wsum[w] = x;
    __syncthreads();
    if (w == 0) {
        int s = (lane < SCAN_BS / 32) ? wsum[lane] : 0;
#pragma unroll
        for (int o = 1; o < SCAN_BS / 32; o <<= 1) {
            int y = __shfl_up_sync(0xffffffffu, s, o);
            if (lane >= o) s += y;
        }
        if (lane < SCAN_BS / 32) wsum[lane] = s;
    }
    __syncthreads();
    int incl = x + (w > 0 ? wsum[w - 1] : 0);
    int total = wsum[SCAN_BS / 32 - 1];

    if (tid == 0) {
        unsigned long long pub =
            ((unsigned long long)(bid == 0 ? 2u : 1u) << 32) | (unsigned)total;
        atomicExch(&g_state[bid], pub);
    }

    if (w == 0) {
        int prefix = 0;
        if (bid > 0) {
            int p = bid - 1;
            while (true) {
                int idx = p - lane;
                unsigned long long st =
                    (idx >= 0) ? atomicAdd(&g_state[idx], 0ULL) : (2ULL << 32);
                unsigned status = (unsigned)(st >> 32);
                unsigned inval = __ballot_sync(0xffffffffu, status == 0u);
                if (inval) continue;
                int val = (int)(unsigned)st;
                unsigned inclm = __ballot_sync(0xffffffffu, status == 2u);
                int contrib;
                if (inclm) {
                    int firstI = __ffs(inclm) - 1;
                    contrib = (lane <= firstI) ? val : 0;
                } else {
                    contrib = val;
                }
#pragma unroll
                for (int o = 16; o > 0; o >>= 1)
                    contrib += __shfl_down_sync(0xffffffffu, contrib, o);
                contrib = __shfl_sync(0xffffffffu, contrib, 0);
                prefix += contrib;
                if (inclm) break;
                p -= 32;
            }
            if (lane == 0) {
                unsigned long long pub =
                    (2ULL << 32) | (unsigned)(prefix + total);
                atomicExch(&g_state[bid], pub);
            }
        }
        if (lane == 0) sprefix = prefix;
    }
    __syncthreads();
    int pfx = sprefix;
    if (i < nNodes) {
        int inclG = pfx + incl;
        g_rowptr[i + 1] = inclG;
        g_cursor[i] = inclG - v;
        if (i == 0) g_rowptr[0] = 0;
    }
}

// ---------------- CSR fill (4 edges per thread) -----------------------------
__global__ void __launch_bounds__(256) fill_kernel(const void* __restrict__ ei,
                                                   int nE) {
    int t = blockIdx.x * 256 + threadIdx.x;
    int e = t * 4;
    if (e >= nE) return;
    int s[4], d[4];
    int cnt;
    if (g_e64) {
        const long long* p = (const long long*)ei;
        if (e + 3 < nE) {
            longlong2 sa = *(const longlong2*)(p + e);
            longlong2 sb = *(const longlong2*)(p + e + 2);
            longlong2 da = *(const longlong2*)(p + nE + e);
            longlong2 db = *(const longlong2*)(p + nE + e + 2);
            s[0] = (int)sa.x; s[1] = (int)sa.y; s[2] = (int)sb.x; s[3] = (int)sb.y;
            d[0] = (int)da.x; d[1] = (int)da.y; d[2] = (int)db.x; d[3] = (int)db.y;
            cnt = 4;
        } else {
            cnt = nE - e;
            for (int k = 0; k < cnt; k++) {
                s[k] = (int)p[e + k];
                d[k] = (int)p[nE + e + k];
            }
        }
    } else {
        const int* p = (const int*)ei;
        if (e + 3 < nE) {
            int4 sa = *(const int4*)(p + e);
            int4 da = *(const int4*)(p + nE + e);
            s[0] = sa.x; s[1] = sa.y; s[2] = sa.z; s[3] = sa.w;
            d[0] = da.x; d[1] = da.y; d[2] = da.z; d[3] = da.w;
            cnt = 4;
        } else {
            cnt = nE - e;
            for (int k = 0; k < cnt; k++) {
                s[k] = p[e + k];
                d[k] = p[nE + e + k];
            }
        }
    }
#pragma unroll
    for (int k = 0; k < 4; k++) {
        if (k < cnt) {
            int pos = atomicAdd(&g_cursor[d[k]], 1);
            g_csr[pos] = s[k];
        }
    }
}

// ---------------- batched 64->64 dense: 16 nodes per warp ------------------
__device__ __forceinline__ void dense64x16(
    const float* __restrict__ sW, unsigned long long bias,
    const float (*__restrict__ sx)[F], unsigned long long acc[16], int lane) {
#pragma unroll
    for (int nb = 0; nb < 16; nb++) acc[nb] = bias;
#pragma unroll 4
    for (int k4 = 0; k4 < 16; k4++) {
        const float* wr = sW + (k4 * 4) * F + 2 * lane;
        unsigned long long w0 = *(const unsigned long long*)(wr);
        unsigned long long w1 = *(const unsigned long long*)(wr + F);
        unsigned long long w2 = *(const unsigned long long*)(wr + 2 * F);
        unsigned long long w3 = *(const unsigned long long*)(wr + 3 * F);
#pragma unroll
        for (int nb = 0; nb < 16; nb++) {
            float4 iv = *(const float4*)&sx[nb][k4 * 4];
            acc[nb] = ffma2(w0, splat2(iv.x), acc[nb]);
            acc[nb] = ffma2(w1, splat2(iv.y), acc[nb]);
            acc[nb] = ffma2(w2, splat2(iv.z), acc[nb]);
            acc[nb] = ffma2(w3, splat2(iv.w), acc[nb]);
        }
    }
}

// ---------------- FUSED layer: gather (CSR) + MLP + optional pool ----------
// Block = 128 threads = 4 warps; each warp owns a 16-node tile: gathers
// agg = x + sum_neighbors directly into its SMEM tile, then runs the MLP.
// Memory-phase warps and FMA-phase warps overlap across the SM.
template <bool POOL>
__global__ void __launch_bounds__(128) fused_layer_kernel(
    const float* __restrict__ feat,
    const float* __restrict__ W1, const float* __restrict__ b1,
    const float* __restrict__ W2, const float* __restrict__ b2,
    float* __restrict__ hout,
    const void* __restrict__ batch,
    const float* __restrict__ fcW,
    int nNodes) {
    __shared__ float sW1[F * F];                    // 16 KB
    __shared__ float sW2[F * F];                    // 16 KB
    __shared__ __align__(16) float sX[4][16][F];    // 16 KB

    int tid = threadIdx.x;
    for (int i = tid; i < F * F / 4; i += 128) {
        ((float4*)sW1)[i] = ((const float4*)W1)[i];
        ((float4*)sW2)[i] = ((const float4*)W2)[i];
    }
    __syncthreads();

    int warp = tid >> 5, lane = tid & 31;
    int half = lane >> 4, c = lane & 15;
    float(*sx)[F] = sX[warp];

    float2 bv1 = *(const float2*)(b1 + 2 * lane);
    float2 bv2 = *(const float2*)(b2 + 2 * lane);
    unsigned long long bias1 = pack2(bv1.x, bv1.y);
    unsigned long long bias2 = pack2(bv2.x, bv2.y);
    float fc0 = 0.f, fc1 = 0.f;
    int b64 = 0;
    if (POOL) {
        float2 fv = *(const float2*)(fcW + 2 * lane);
        fc0 = fv.x; fc1 = fv.y;
        b64 = g_b64;
    }

    int base = (blockIdx.x * 4 + warp) * 16;
    if (base >= nNodes) return;

    // ---- gather phase: agg rows for 16 nodes into sx ----
    for (int nb = 0; nb < 16; nb++) {
        int node = base + nb;
        float4 acc = make_float4(0.f, 0.f, 0.f, 0.f);
        if (node < nNodes) {
            int off = g_rowptr[node];
            int deg = g_rowptr[node + 1] - off;
            if (half == 0)
                acc = *((const float4*)(feat + (size_t)node * F) + c);
            for (int be = 0; be < deg; be += 32) {
                int cnt = min(deg - be, 32);
                int idx = 0;
                if (lane < cnt) idx = g_csr[off + be + lane];
                int iters = (cnt + 1) >> 1;
                int t = 0;
                for (; t + 2 <= iters; t += 2) {
                    int k0 = 2 * t + half;
                    int s0 = __shfl_sync(0xffffffffu, idx, k0);
                    int s1 = __shfl_sync(0xffffffffu, idx, k0 + 2);
                    float4 v0 = *((const float4*)(feat + (size_t)s0 * F) + c);
                    float4 v1 = (k0 + 2 < cnt)
                                    ? *((const float4*)(feat + (size_t)s1 * F) + c)
                                    : make_float4(0.f, 0.f, 0.f, 0.f);
                    acc.x += v0.x; acc.y += v0.y; acc.z += v0.z; acc.w += v0.w;
                    acc.x += v1.x; acc.y += v1.y; acc.z += v1.z; acc.w += v1.w;
                }
                for (; t < iters; t++) {
                    int k = 2 * t + half;
                    int s = __shfl_sync(0xffffffffu, idx, k & 31);
                    if (k < cnt) {
                        float4 v = *((const float4*)(feat + (size_t)s * F) + c);
                        acc.x += v.x; acc.y += v.y; acc.z += v.z; acc.w += v.w;
                    }
                }
            }
        }
        acc.x += __shfl_down_sync(0xffffffffu, acc.x, 16);
        acc.y += __shfl_down_sync(0xffffffffu, acc.y, 16);
        acc.z += __shfl_down_sync(0xffffffffu, acc.z, 16);
        acc.w += __shfl_down_sync(0xffffffffu, acc.w, 16);
        if (half == 0) *(float4*)&sx[nb][c * 4] = acc;
    }
    __syncwarp();

    // ---- MLP phase ----
    unsigned long long acc[16];
    dense64x16(sW1, bias1, (const float(*)[F])sx, acc, lane);
    __syncwarp();
#pragma unroll
    for (int nb = 0; nb < 16; nb++) {
        float a, b;
        unpack2(acc[nb], a, b);
        *(float2*)&sx[nb][2 * lane] = make_float2(fmaxf(a, 0.f), fmaxf(b, 0.f));
    }
    __syncwarp();
    dense64x16(sW2, bias2, (const float(*)[F])sx, acc, lane);

    if (POOL) {
#pragma unroll
        for (int nb = 0; nb < 16; nb++) {
            float a, b;
            unpack2(acc[nb], a, b);
            float s = fmaxf(a, 0.f) * fc0 + fmaxf(b, 0.f) * fc1;
#pragma unroll
            for (int o = 16; o > 0; o >>= 1)
                s += __shfl_down_sync(0xffffffffu, s, o);
            if (lane == 0) {
                int node = base + nb;
                if (node < nNodes) {
                    int g = b64 ? (int)((const long long*)batch)[node]
                                : ((const int*)batch)[node];
                    atomicAdd(&g_sum[g], s);
                    atomicAdd(&g_cnt[g], 1.f);
                }
            }
        }
    } else {
#pragma unroll
        for (int nb = 0; nb < 16; nb++) {
            int node = base + nb;
            if (node < nNodes) {
                float a, b;
                unpack2(acc[nb], a, b);
                *(float2*)&hout[(size_t)node * F + 2 * lane] =
                    make_float2(fmaxf(a, 0.f), fmaxf(b, 0.f));
            }
        }
    }
}

// ---------------- final: out[g] = sum/cnt + fcb -----------------------------
__global__ void final_kernel(float* __restrict__ out,
                             const float* __restrict__ fcb) {
    int g = threadIdx.x;
    if (g < N_GRAPHS)
        out[g] = g_sum[g] / fmaxf(g_cnt[g], 1.f) + fcb[0];
}

// ---------------- launch -----------------------------------------------------
extern "C" void kernel_launch(void* const* d_in, const int* in_sizes, int n_in,
                              void* d_out, int out_size) {
    const float* x    = (const float*)d_in[0];
    const void*  ei   = d_in[1];
    const void*  bat  = d_in[2];
    const float* W1_0 = (const float*)d_in[3];
    const float* b1_0 = (const float*)d_in[4];
    const float* W2_0 = (const float*)d_in[5];
    const float* b2_0 = (const float*)d_in[6];
    const float* W1_1 = (const float*)d_in[7];
    const float* b1_1 = (const float*)d_in[8];
    const float* W2_1 = (const float*)d_in[9];
    const float* b2_1 = (const float*)d_in[10];
    const float* fcW  = (const float*)d_in[11];
    const float* fcb  = (const float*)d_in[12];

    int E = in_sizes[1] / 2;
    int N = in_sizes[2];

    float* h_p = nullptr;
    cudaGetSymbolAddress((void**)&h_p, g_h);

    int nb = (N + 255) / 256;
    int eb4 = (E / 4 + 256) / 256;
    int sblocks = (N + SCAN_BS - 1) / SCAN_BS;
    int fb = (N + 63) / 64;

    // ---- CSR build (shared by both layers) ----
    init_kernel<<<nb, 256>>>(ei, bat, N);
    hist_kernel<<<eb4, 256>>>(ei, E);
    scan_kernel<<<sblocks, SCAN_BS>>>(N);
    fill_kernel<<<eb4, 256>>>(ei, E);

    // ---- layer 1 (gather + MLP fused) ----
    fused_layer_kernel<false><<<fb, 128>>>(x, W1_0, b1_0, W2_0, b2_0, h_p, bat,
                                           fcW, N);

    // ---- layer 2 (gather + MLP + pooling fused) ----
    fused_layer_kernel<true><<<fb, 128>>>(h_p, W1_1, b1_1, W2_1, b2_1, nullptr,
                                          bat, fcW, N);

    final_kernel<<<1, 64>>>((float*)d_out, fcb);
}

// round 7
// speedup vs baseline: 1.2542x; 1.2542x over previous
#include <cuda_runtime.h>
#include <cuda_fp16.h>

#define N_NODES_MAX 100000
#define N_EDGES_MAX 1300000
#define F 64
#define N_GRAPHS 64
#define SCAN_BS 512

// ---------------- scratch (static device globals; no allocs allowed) -------
__device__ float  g_agg[(size_t)N_NODES_MAX * F];  // 25.6 MB fp32 agg
__device__ __half g_xh[(size_t)N_NODES_MAX * F];   // 12.8 MB fp16 x
__device__ __half g_hh[(size_t)N_NODES_MAX * F];   // 12.8 MB fp16 h (layer1 out)
__device__ int   g_deg[N_NODES_MAX];
__device__ int   g_rowptr[N_NODES_MAX + 1];
__device__ int   g_cursor[N_NODES_MAX];
__device__ int   g_csr[N_EDGES_MAX];               // src ids grouped by dst
__device__ unsigned long long g_state[512];        // lookback scan states
__device__ float g_sum[N_GRAPHS];
__device__ float g_cnt[N_GRAPHS];
__device__ int   g_e64;   // 1 if edge_index is int64, else int32
__device__ int   g_b64;   // 1 if batch is int64, else int32

// ---------------- packed f32x2 helpers (FFMA2 path, sm_103a) ---------------
__device__ __forceinline__ unsigned long long pack2(float a, float b) {
    unsigned long long r;
    asm("mov.b64 %0, {%1, %2};" : "=l"(r) : "f"(a), "f"(b));
    return r;
}
__device__ __forceinline__ unsigned long long splat2(float a) {
    unsigned long long r;
    asm("mov.b64 %0, {%1, %1};" : "=l"(r) : "f"(a));
    return r;
}
__device__ __forceinline__ void unpack2(unsigned long long v, float& a, float& b) {
    asm("mov.b64 {%0, %1}, %2;" : "=f"(a), "=f"(b) : "l"(v));
}
__device__ __forceinline__ unsigned long long ffma2(unsigned long long a,
                                                    unsigned long long b,
                                                    unsigned long long c) {
    unsigned long long r;
    asm("fma.rn.f32x2 %0, %1, %2, %3;" : "=l"(r) : "l"(a), "l"(b), "l"(c));
    return r;
}

// ---------------- init: zero deg/state/pool + dtype detection --------------
__global__ void init_kernel(const void* __restrict__ ei,
                            const void* __restrict__ batch, int nNodes) {
    int i = blockIdx.x * blockDim.x + threadIdx.x;
    if (i < nNodes) g_deg[i] = 0;
    if (i < N_GRAPHS) {
        g_sum[i] = 0.f;
        g_cnt[i] = 0.f;
    }
    if (i < 512) g_state[i] = 0ULL;
    if (i == 0) {
        const long long* p = (const long long*)ei;
        bool ok = true;
        for (int k = 0; k < 4; k++) {
            long long v = p[k];
            if (v < 0 || v >= N_NODES_MAX) ok = false;
        }
        g_e64 = ok ? 1 : 0;
        const long long* q = (const long long*)batch;
        int M = nNodes / 2;
        bool okb = true;
        for (int k = M - 4; k < M; k++) {
            long long v = q[k];
            if (v < 0 || v >= N_GRAPHS) okb = false;
        }
        g_b64 = okb ? 1 : 0;
    }
}

// ---------------- fp32 -> fp16 convert (8 elems per thread) ----------------
__global__ void __launch_bounds__(256) convert_kernel(
    const float* __restrict__ src, __half* __restrict__ dst, int n8) {
    int i = blockIdx.x * 256 + threadIdx.x;
    if (i >= n8) return;
    float4 a = ((const float4*)src)[2 * i];
    float4 b = ((const float4*)src)[2 * i + 1];
    __half2 h0 = __floats2half2_rn(a.x, a.y);
    __half2 h1 = __floats2half2_rn(a.z, a.w);
    __half2 h2 = __floats2half2_rn(b.x, b.y);
    __half2 h3 = __floats2half2_rn(b.z, b.w);
    uint4 o;
    o.x = *(unsigned*)&h0;
    o.y = *(unsigned*)&h1;
    o.z = *(unsigned*)&h2;
    o.w = *(unsigned*)&h3;
    ((uint4*)dst)[i] = o;
}

// ---------------- histogram of dst (4 edges per thread) --------------------
__global__ void __launch_bounds__(256) hist_kernel(const void* __restrict__ ei,
                                                   int nE) {
    int t = blockIdx.x * 256 + threadIdx.x;
    int e = t * 4;
    if (e >= nE) return;
    if (g_e64) {
        const long long* d = (const long long*)ei + nE;
        if (e + 3 < nE) {
            longlong2 a = *(const longlong2*)(d + e);
            longlong2 b = *(const longlong2*)(d + e + 2);
            atomicAdd(&g_deg[(int)a.x], 1);
            atomicAdd(&g_deg[(int)a.y], 1);
            atomicAdd(&g_deg[(int)b.x], 1);
            atomicAdd(&g_deg[(int)b.y], 1);
        } else {
            for (int k = e; k < nE; k++) atomicAdd(&g_deg[(int)d[k]], 1);
        }
    } else {
        const int* d = (const int*)ei + nE;
        if (e + 3 < nE) {
            int4 a = *(const int4*)(d + e);
            atomicAdd(&g_deg[a.x], 1);
            atomicAdd(&g_deg[a.y], 1);
            atomicAdd(&g_deg[a.z], 1);
            atomicAdd(&g_deg[a.w], 1);
        } else {
            for (int k = e; k < nE; k++) atomicAdd(&g_deg[d[k]], 1);
        }
    }
}

// ---------------- single-pass scan (decoupled lookback) --------------------
__global__ void __launch_bounds__(SCAN_BS) scan_kernel(int nNodes) {
    int tid = threadIdx.x, bid = blockIdx.x;
    int lane = tid & 31, w = tid >> 5;
    int i = bid * SCAN_BS + tid;
    int v = (i < nNodes) ? g_deg[i] : 0;

    int x = v;
#pragma unroll
    for (int o = 1; o < 32; o <<= 1) {
        int y = __shfl_up_sync(0xffffffffu, x, o);
        if (lane >= o) x += y;
    }
    __shared__ int wsum[SCAN_BS / 32];
    __shared__ int sprefix;
    if (lane == 31) wsum[w] = x;
    __syncthreads();
    if (w == 0) {
        int s = (lane < SCAN_BS / 32) ? wsum[lane] : 0;
#pragma unroll
        for (int o = 1; o < SCAN_BS / 32; o <<= 1) {
            int y = __shfl_up_sync(0xffffffffu, s, o);
            if (lane >= o) s += y;
        }
        if (lane < SCAN_BS / 32) wsum[lane] = s;
    }
    __syncthreads();
    int incl = x + (w > 0 ? wsum[w - 1] : 0);
    int total = wsum[SCAN_BS / 32 - 1];

    if (tid == 0) {
        unsigned long long pub =
            ((unsigned long long)(bid == 0 ? 2u : 1u) << 32) | (unsigned)total;
        atomicExch(&g_state[bid], pub);
    }

    if (w == 0) {
        int prefix = 0;
        if (bid > 0) {
            int p = bid - 1;
            while (true) {
                int idx = p - lane;
                unsigned long long st =
                    (idx >= 0) ? atomicAdd(&g_state[idx], 0ULL) : (2ULL << 32);
                unsigned status = (unsigned)(st >> 32);
                unsigned inval = __ballot_sync(0xffffffffu, status == 0u);
                if (inval) continue;
                int val = (int)(unsigned)st;
                unsigned inclm = __ballot_sync(0xffffffffu, status == 2u);
                int contrib;
                if (inclm) {
                    int firstI = __ffs(inclm) - 1;
                    contrib = (lane <= firstI) ? val : 0;
                } else {
                    contrib = val;
                }
#pragma unroll
                for (int o = 16; o > 0; o >>= 1)
                    contrib += __shfl_down_sync(0xffffffffu, contrib, o);
                contrib = __shfl_sync(0xffffffffu, contrib, 0);
                prefix += contrib;
                if (inclm) break;
                p -= 32;
            }
            if (lane == 0) {
                unsigned long long pub =
                    (2ULL << 32) | (unsigned)(prefix + total);
                atomicExch(&g_state[bid], pub);
            }
        }
        if (lane == 0) sprefix = prefix;
    }
    __syncthreads();
    int pfx = sprefix;
    if (i < nNodes) {
        int inclG = pfx + incl;
        g_rowptr[i + 1] = inclG;
        g_cursor[i] = inclG - v;
        if (i == 0) g_rowptr[0] = 0;
    }
}

// ---------------- CSR fill (4 edges per thread) -----------------------------
__global__ void __launch_bounds__(256) fill_kernel(const void* __restrict__ ei,
                                                   int nE) {
    int t = blockIdx.x * 256 + threadIdx.x;
    int e = t * 4;
    if (e >= nE) return;
    int s[4], d[4];
    int cnt;
    if (g_e64) {
        const long long* p = (const long long*)ei;
        if (e + 3 < nE) {
            longlong2 sa = *(const longlong2*)(p + e);
            longlong2 sb = *(const longlong2*)(p + e + 2);
            longlong2 da = *(const longlong2*)(p + nE + e);
            longlong2 db = *(const longlong2*)(p + nE + e + 2);
            s[0] = (int)sa.x; s[1] = (int)sa.y; s[2] = (int)sb.x; s[3] = (int)sb.y;
            d[0] = (int)da.x; d[1] = (int)da.y; d[2] = (int)db.x; d[3] = (int)db.y;
            cnt = 4;
        } else {
            cnt = nE - e;
            for (int k = 0; k < cnt; k++) {
                s[k] = (int)p[e + k];
                d[k] = (int)p[nE + e + k];
            }
        }
    } else {
        const int* p = (const int*)ei;
        if (e + 3 < nE) {
            int4 sa = *(const int4*)(p + e);
            int4 da = *(const int4*)(p + nE + e);
            s[0] = sa.x; s[1] = sa.y; s[2] = sa.z; s[3] = sa.w;
            d[0] = da.x; d[1] = da.y; d[2] = da.z; d[3] = da.w;
            cnt = 4;
        } else {
            cnt = nE - e;
            for (int k = 0; k < cnt; k++) {
                s[k] = p[e + k];
                d[k] = p[nE + e + k];
            }
        }
    }
#pragma unroll
    for (int k = 0; k < 4; k++) {
        if (k < cnt) {
            int pos = atomicAdd(&g_cursor[d[k]], 1);
            g_csr[pos] = s[k];
        }
    }
}

// ---------------- gather (fp16 in, fp32 out) --------------------------------
// out[i] = feat16[i] + sum_{j in N(i)} feat16[j], accumulated in fp32.
// Warp per node; halves process alternating edges; lane reads uint2 = 4 halves.
__global__ void __launch_bounds__(256) gather_kernel(
    const __half* __restrict__ feat, float* __restrict__ out, int nNodes) {
    int warp = threadIdx.x >> 5, lane = threadIdx.x & 31;
    int i = blockIdx.x * 8 + warp;
    if (i >= nNodes) return;
    int off = g_rowptr[i];
    int deg = g_rowptr[i + 1] - off;
    int half = lane >> 4, c = lane & 15;

    float4 acc = make_float4(0.f, 0.f, 0.f, 0.f);
    if (half == 0) {
        uint2 h = *((const uint2*)(feat + (size_t)i * F) + c);
        float2 f0 = __half22float2(*(const __half2*)&h.x);
        float2 f1 = __half22float2(*(const __half2*)&h.y);
        acc.x = f0.x; acc.y = f0.y; acc.z = f1.x; acc.w = f1.y;
    }

    for (int base = 0; base < deg; base += 32) {
        int cnt = min(deg - base, 32);
        int idx = 0;
        if (lane < cnt) idx = g_csr[off + base + lane];
        int iters = (cnt + 1) >> 1;
        for (int t = 0; t < iters; t++) {
            int k = 2 * t + half;
            int s = __shfl_sync(0xffffffffu, idx, k & 31);
            if (k < cnt) {
                uint2 h = *((const uint2*)(feat + (size_t)s * F) + c);
                float2 f0 = __half22float2(*(const __half2*)&h.x);
                float2 f1 = __half22float2(*(const __half2*)&h.y);
                acc.x += f0.x; acc.y += f0.y; acc.z += f1.x; acc.w += f1.y;
            }
        }
    }
    acc.x += __shfl_down_sync(0xffffffffu, acc.x, 16);
    acc.y += __shfl_down_sync(0xffffffffu, acc.y, 16);
    acc.z += __shfl_down_sync(0xffffffffu, acc.z, 16);
    acc.w += __shfl_down_sync(0xffffffffu, acc.w, 16);
    if (half == 0)
        *((float4*)(out + (size_t)i * F) + c) = acc;
}

// ---------------- batched 64->64 dense: 16 nodes per warp ------------------
__device__ __forceinline__ void dense64x16(
    const float* __restrict__ sW, unsigned long long bias,
    const float (*__restrict__ sx)[F], unsigned long long acc[16], int lane) {
#pragma unroll
    for (int nb = 0; nb < 16; nb++) acc[nb] = bias;
#pragma unroll 4
    for (int k4 = 0; k4 < 16; k4++) {
        const float* wr = sW + (k4 * 4) * F + 2 * lane;
        unsigned long long w0 = *(const unsigned long long*)(wr);
        unsigned long long w1 = *(const unsigned long long*)(wr + F);
        unsigned long long w2 = *(const unsigned long long*)(wr + 2 * F);
        unsigned long long w3 = *(const unsigned long long*)(wr + 3 * F);
#pragma unroll
        for (int nb = 0; nb < 16; nb++) {
            float4 iv = *(const float4*)&sx[nb][k4 * 4];
            acc[nb] = ffma2(w0, splat2(iv.x), acc[nb]);
            acc[nb] = ffma2(w1, splat2(iv.y), acc[nb]);
            acc[nb] = ffma2(w2, splat2(iv.z), acc[nb]);
            acc[nb] = ffma2(w3, splat2(iv.w), acc[nb]);
        }
    }
}

// ---------------- fused GIN MLP: out = relu(relu(in@W1+b1)@W2+b2) ----------
// POOL=false: writes h as fp16 (for the next layer's gather).
// POOL=true : accumulates dot(h2, fcW) per graph.
template <bool POOL>
__global__ void __launch_bounds__(128) mlp_kernel(
    const float* __restrict__ xin,
    const float* __restrict__ W1, const float* __restrict__ b1,
    const float* __restrict__ W2, const float* __restrict__ b2,
    __half* __restrict__ hout,
    const void* __restrict__ batch,
    const float* __restrict__ fcW,
    int nNodes) {
    __shared__ float sW1[F * F];                    // 16 KB
    __shared__ float sW2[F * F];                    // 16 KB
    __shared__ __align__(16) float sX[4][16][F];    // 16 KB

    int tid = threadIdx.x;
    for (int i = tid; i < F * F / 4; i += 128) {
        ((float4*)sW1)[i] = ((const float4*)W1)[i];
        ((float4*)sW2)[i] = ((const float4*)W2)[i];
    }
    __syncthreads();

    int warp = tid >> 5, lane = tid & 31;
    float(*sx)[F] = sX[warp];

    float2 bv1 = *(const float2*)(b1 + 2 * lane);
    float2 bv2 = *(const float2*)(b2 + 2 * lane);
    unsigned long long bias1 = pack2(bv1.x, bv1.y);
    unsigned long long bias2 = pack2(bv2.x, bv2.y);
    float fc0 = 0.f, fc1 = 0.f;
    int b64 = 0;
    if (POOL) {
        float2 fv = *(const float2*)(fcW + 2 * lane);
        fc0 = fv.x; fc1 = fv.y;
        b64 = g_b64;
    }

    for (int it = 0; it < 2; it++) {
        int base = (blockIdx.x * 8 + warp * 2 + it) * 16;
        if (base >= nNodes) break;

#pragma unroll
        for (int i = 0; i < 8; i++) {
            int idx = lane + 32 * i;  // 0..255 float4 slots
            int nb = idx >> 4, c = idx & 15;
            int node = base + nb;
            float4 v = (node < nNodes)
                           ? *((const float4*)(xin + (size_t)node * F) + c)
                           : make_float4(0.f, 0.f, 0.f, 0.f);
            *(float4*)&sx[nb][c * 4] = v;
        }
        __syncwarp();

        unsigned long long acc[16];
        dense64x16(sW1, bias1, (const float(*)[F])sx, acc, lane);
        __syncwarp();
#pragma unroll
        for (int nb = 0; nb < 16; nb++) {
            float a, b;
            unpack2(acc[nb], a, b);
            *(float2*)&sx[nb][2 * lane] =
                make_float2(fmaxf(a, 0.f), fmaxf(b, 0.f));
        }
        __syncwarp();
        dense64x16(sW2, bias2, (const float(*)[F])sx, acc, lane);
        __syncwarp();

        if (POOL) {
#pragma unroll
            for (int nb = 0; nb < 16; nb++) {
                float a, b;
                unpack2(acc[nb], a, b);
                float s = fmaxf(a, 0.f) * fc0 + fmaxf(b, 0.f) * fc1;
#pragma unroll
                for (int o = 16; o > 0; o >>= 1)
                    s += __shfl_down_sync(0xffffffffu, s, o);
                if (lane == 0) {
                    int node = base + nb;
                    if (node < nNodes) {
                        int g = b64 ? (int)((const long long*)batch)[node]
                                    : ((const int*)batch)[node];
                        atomicAdd(&g_sum[g], s);
                        atomicAdd(&g_cnt[g], 1.f);
                    }
                }
            }
        } else {
#pragma unroll
            for (int nb = 0; nb < 16; nb++) {
                int node = base + nb;
                if (node < nNodes) {
                    float a, b;
                    unpack2(acc[nb], a, b);
                    __half2 hv =
                        __floats2half2_rn(fmaxf(a, 0.f), fmaxf(b, 0.f));
                    ((__half2*)(hout + (size_t)node * F))[lane] = hv;
                }
            }
        }
    }
}

// ---------------- final: out[g] = sum/cnt + fcb -----------------------------
__global__ void final_kernel(float* __restrict__ out,
                             const float* __restrict__ fcb) {
    int g = threadIdx.x;
    if (g < N_GRAPHS)
        out[g] = g_sum[g] / fmaxf(g_cnt[g], 1.f) + fcb[0];
}

// ---------------- launch -----------------------------------------------------
extern "C" void kernel_launch(void* const* d_in, const int* in_sizes, int n_in,
                              void* d_out, int out_size) {
    const float* x    = (const float*)d_in[0];
    const void*  ei   = d_in[1];
    const void*  bat  = d_in[2];
    const float* W1_0 = (const float*)d_in[3];
    const float* b1_0 = (const float*)d_in[4];
    const float* W2_0 = (const float*)d_in[5];
    const float* b2_0 = (const float*)d_in[6];
    const float* W1_1 = (const float*)d_in[7];
    const float* b1_1 = (const float*)d_in[8];
    const float* W2_1 = (const float*)d_in[9];
    const float* b2_1 = (const float*)d_in[10];
    const float* fcW  = (const float*)d_in[11];
    const float* fcb  = (const float*)d_in[12];

    int E = in_sizes[1] / 2;
    int N = in_sizes[2];

    float*  agg_p = nullptr;
    __half *xh_p = nullptr, *hh_p = nullptr;
    cudaGetSymbolAddress((void**)&agg_p, g_agg);
    cudaGetSymbolAddress((void**)&xh_p, g_xh);
    cudaGetSymbolAddress((void**)&hh_p, g_hh);

    int nb = (N + 255) / 256;
    int eb4 = (E / 4 + 256) / 256;
    int sblocks = (N + SCAN_BS - 1) / SCAN_BS;
    int gb = (N + 7) / 8;
    int mb = (N + 127) / 128;   // 128 nodes per mlp block (4 warps x 2 x 16)
    int n8 = N * F / 8;
    int cb = (n8 + 255) / 256;

    // ---- CSR build (shared by both layers) + x fp16 convert ----
    init_kernel<<<nb, 256>>>(ei, bat, N);
    hist_kernel<<<eb4, 256>>>(ei, E);
    convert_kernel<<<cb, 256>>>(x, xh_p, n8);
    scan_kernel<<<sblocks, SCAN_BS>>>(N);
    fill_kernel<<<eb4, 256>>>(ei, E);

    // ---- layer 1 ----
    gather_kernel<<<gb, 256>>>(xh_p, agg_p, N);
    mlp_kernel<false><<<mb, 128>>>(agg_p, W1_0, b1_0, W2_0, b2_0, hh_p, bat,
                                   fcW, N);

    // ---- layer 2 (+ fused pooling projection) ----
    gather_kernel<<<gb, 256>>>(hh_p, agg_p, N);
    mlp_kernel<true><<<mb, 128>>>(agg_p, W1_1, b1_1, W2_1, b2_1, nullptr, bat,
                                  fcW, N);

    final_kernel<<<1, 64>>>((float*)d_out, fcb);
}